// round 1
// baseline (speedup 1.0000x reference)
#include <cuda_runtime.h>
#include <cuda_bf16.h>

#define N 4096
#define FIN 512
#define FOUT 256
#define ALPHA 0.2f

// ---------------- scratch (device globals; no allocations allowed) ----------
__device__ float g_wh[N * FOUT];          // 4 MB  projected features
__device__ float g_fsrc[N];               // wh @ a1 + a_b
__device__ float g_fdst[N];               // wh @ a2
__device__ float g_mi[N];                 // row max logit
__device__ float g_rz[N];                 // 1 / Z_i
__device__ unsigned g_mask[N * (N / 32)]; // bit-packed adj, 2 MB

// ---------------- f32x2 packed-FMA helpers (sm_103a) ------------------------
__device__ __forceinline__ unsigned long long pk(float lo, float hi) {
    unsigned long long r;
    asm("mov.b64 %0, {%1,%2};" : "=l"(r) : "f"(lo), "f"(hi));
    return r;
}
__device__ __forceinline__ unsigned long long f2fma(unsigned long long a,
                                                    unsigned long long b,
                                                    unsigned long long c) {
    unsigned long long d;
    asm("fma.rn.f32x2 %0, %1, %2, %3;" : "=l"(d) : "l"(a), "l"(b), "l"(c));
    return d;
}
__device__ __forceinline__ float lof(unsigned long long v) {
    return __uint_as_float((unsigned)v);
}
__device__ __forceinline__ float hif(unsigned long long v) {
    return __uint_as_float((unsigned)(v >> 32));
}

// ---------------- kernel 1: wh = h @ W + b  (4096x512x256, fp32/f32x2) ------
// block 256 thr, tile 64(M) x 64(N), BK=32; each thread 4x4 via 2x f32x2 cols
__global__ __launch_bounds__(256) void k_gemm_wh(const float* __restrict__ h,
                                                 const float* __restrict__ Wm,
                                                 const float* __restrict__ bias) {
    __shared__ float As[64][33];  // h tile  [m][k], padded
    __shared__ float Bs[32][64];  // W tile  [k][n]

    const int t = threadIdx.x;
    const int m0 = blockIdx.x * 64;
    const int n0 = blockIdx.y * 64;
    const int tx = t & 15;   // 16 col groups of 4
    const int ty = t >> 4;   // 16 row groups of 4

    unsigned long long acc2[4][2];
#pragma unroll
    for (int i = 0; i < 4; i++) { acc2[i][0] = 0ull; acc2[i][1] = 0ull; }

    for (int k0 = 0; k0 < FIN; k0 += 32) {
        // load A tile: 64x32 = 512 float4
#pragma unroll
        for (int u = 0; u < 2; u++) {
            int idx = t + u * 256;
            int r = idx >> 3, c = (idx & 7) * 4;
            float4 v = *(const float4*)(h + (size_t)(m0 + r) * FIN + k0 + c);
            As[r][c] = v.x; As[r][c + 1] = v.y; As[r][c + 2] = v.z; As[r][c + 3] = v.w;
        }
        // load B tile: 32x64 = 512 float4
#pragma unroll
        for (int u = 0; u < 2; u++) {
            int idx = t + u * 256;
            int r = idx >> 4, c = (idx & 15) * 4;
            *(float4*)(&Bs[r][c]) = *(const float4*)(Wm + (size_t)(k0 + r) * FOUT + n0 + c);
        }
        __syncthreads();

#pragma unroll
        for (int k = 0; k < 32; k++) {
            double2 bd = *(const double2*)(&Bs[k][tx * 4]);
            unsigned long long b01 = __double_as_longlong(bd.x);
            unsigned long long b23 = __double_as_longlong(bd.y);
#pragma unroll
            for (int i = 0; i < 4; i++) {
                float a = As[ty * 4 + i][k];
                unsigned long long ap = pk(a, a);
                acc2[i][0] = f2fma(ap, b01, acc2[i][0]);
                acc2[i][1] = f2fma(ap, b23, acc2[i][1]);
            }
        }
        __syncthreads();
    }

    const int n = n0 + tx * 4;
    float4 bv = *(const float4*)(bias + n);
#pragma unroll
    for (int i = 0; i < 4; i++) {
        float4 o;
        o.x = lof(acc2[i][0]) + bv.x;
        o.y = hif(acc2[i][0]) + bv.y;
        o.z = lof(acc2[i][1]) + bv.z;
        o.w = hif(acc2[i][1]) + bv.w;
        *(float4*)(g_wh + (size_t)(m0 + ty * 4 + i) * FOUT + n) = o;
    }
}

// ---------------- kernel 2: f_src / f_dst (one warp per row) ----------------
__global__ __launch_bounds__(256) void k_fsd(const float* __restrict__ a1,
                                             const float* __restrict__ a2,
                                             const float* __restrict__ ab) {
    const int warp = threadIdx.x >> 5, lane = threadIdx.x & 31;
    const int i = blockIdx.x * 8 + warp;
    const float4* row = (const float4*)(g_wh + (size_t)i * FOUT);
    const float4* A1 = (const float4*)a1;
    const float4* A2 = (const float4*)a2;
    float s1 = 0.f, s2 = 0.f;
#pragma unroll
    for (int u = 0; u < 2; u++) {
        float4 v = row[lane + u * 32];
        float4 x = A1[lane + u * 32];
        float4 y = A2[lane + u * 32];
        s1 += v.x * x.x + v.y * x.y + v.z * x.z + v.w * x.w;
        s2 += v.x * y.x + v.y * y.y + v.z * y.z + v.w * y.w;
    }
#pragma unroll
    for (int o = 16; o; o >>= 1) {
        s1 += __shfl_down_sync(0xffffffffu, s1, o);
        s2 += __shfl_down_sync(0xffffffffu, s2, o);
    }
    if (lane == 0) {
        g_fsrc[i] = s1 + ab[0];  // fold a_b into f_src
        g_fdst[i] = s2;
    }
}

// ---------------- kernel 3: per-row softmax stats + adj bit-pack ------------
// one block (128 thr) per row. Reads adj exactly once (64 MB total).
__global__ __launch_bounds__(128) void k_prep(const int* __restrict__ adj) {
    const int i = blockIdx.x;
    const int t = threadIdx.x;
    const int warp = t >> 5, lane = t & 31;
    const float fs = g_fsrc[i];

    float fd[32];
    unsigned mybits = 0u;
    float mx = -3.4e38f;
    const int* arow = adj + (size_t)i * N;
#pragma unroll
    for (int m = 0; m < 32; m++) {
        int j = m * 128 + t;
        int a = arow[j];
        bool bit = a > 0;
        unsigned word = __ballot_sync(0xffffffffu, bit);
        if (lane == 0) g_mask[(size_t)i * 128 + m * 4 + warp] = word;
        float f = g_fdst[j];
        fd[m] = f;
        if (bit) { mx = fmaxf(mx, f); mybits |= (1u << m); }
    }

    __shared__ float red[128];
    red[t] = mx;
    __syncthreads();
#pragma unroll
    for (int s = 64; s > 0; s >>= 1) {
        if (t < s) red[t] = fmaxf(red[t], red[t + s]);
        __syncthreads();
    }
    float mxall = red[0];
    __syncthreads();

    float xm = fs + mxall;
    float mi = fmaxf(xm, ALPHA * xm);  // leaky_relu (monotone => row max logit)

    float s = 0.f;
#pragma unroll
    for (int m = 0; m < 32; m++) {
        if ((mybits >> m) & 1u) {
            float x = fs + fd[m];
            float l = fmaxf(x, ALPHA * x);
            s += __expf(l - mi);
        }
    }
    red[t] = s;
    __syncthreads();
#pragma unroll
    for (int sN = 64; sN > 0; sN >>= 1) {
        if (t < sN) red[t] += red[t + sN];
        __syncthreads();
    }
    if (t == 0) {
        g_mi[i] = mi;
        g_rz[i] = (red[0] > 0.f) ? (1.f / red[0]) : 0.f;
    }
}

// ---------------- kernel 4: fused attention-weighted GEMM + elu -------------
// grid 128 blocks, 256 thr. Block tile: 32(I) x 256(D), loop J in tiles of 64.
// dynamic smem: wh tile 64KB + packed-w 16KB + small.
__global__ __launch_bounds__(256) void k_attn(float* __restrict__ out) {
    extern __shared__ char smem[];
    float* wh_s = (float*)smem;                                    // 64*256 f32 = 64KB
    unsigned long long* w2 = (unsigned long long*)(smem + 65536);  // 64*32 u64 = 16KB
    float* fd_s = (float*)(smem + 65536 + 16384);                  // 64
    float* fs_s = fd_s + 64;                                       // 32
    float* mi_s = fs_s + 32;                                       // 32
    float* rz_s = mi_s + 32;                                       // 32
    unsigned* mw_s = (unsigned*)(rz_s + 32);                       // 64

    const int t = threadIdx.x;
    const int i0 = blockIdx.x * 32;

    if (t < 32) {
        fs_s[t] = g_fsrc[i0 + t];
        mi_s[t] = g_mi[i0 + t];
        rz_s[t] = g_rz[i0 + t];
    }

    unsigned long long acc[8][2];
#pragma unroll
    for (int r = 0; r < 8; r++) { acc[r][0] = 0ull; acc[r][1] = 0ull; }

    const int tx = t & 63;   // 64 col groups of 4 (D)
    const int ty = t >> 6;   // 4 row groups of 8 (I)

    __syncthreads();

    for (int j0 = 0; j0 < N; j0 += 64) {
        // load wh tile [64][256] : 4096 float4 / 256 thr = 16 each
        const float4* src = (const float4*)(g_wh + (size_t)j0 * FOUT);
        float4* dst = (float4*)wh_s;
#pragma unroll
        for (int k = 0; k < 16; k++) dst[t + 256 * k] = src[t + 256 * k];
        if (t < 64) fd_s[t] = g_fdst[j0 + t];
        if (t < 64) mw_s[t] = g_mask[(size_t)(i0 + (t >> 1)) * 128 + (j0 >> 5) + (t & 1)];
        __syncthreads();

        // phase 1: compute packed weights w2[jt][r] = (w,w)
        {
            const int r = t & 31, jg = t >> 5;
            const float fs = fs_s[r], mi = mi_s[r], rz = rz_s[r];
            const unsigned w0 = mw_s[r * 2], w1 = mw_s[r * 2 + 1];
            const unsigned wsel = (jg < 4) ? w0 : w1;
#pragma unroll
            for (int k2 = 0; k2 < 8; k2++) {
                int jt = jg * 8 + k2;
                unsigned bit = (wsel >> (jt & 31)) & 1u;
                float x = fs + fd_s[jt];
                float l = fmaxf(x, ALPHA * x);
                float wv = bit ? (__expf(l - mi) * rz) : 0.f;
                w2[jt * 32 + r] = pk(wv, wv);
            }
        }
        __syncthreads();

        // phase 2: acc[32x256] += w[32x64] * wh[64x256]  (packed f32x2 FMA)
#pragma unroll 8
        for (int jt = 0; jt < 64; jt++) {
            double2 vd = *(const double2*)(wh_s + jt * 256 + tx * 4);
            unsigned long long v01 = __double_as_longlong(vd.x);
            unsigned long long v23 = __double_as_longlong(vd.y);
            const double2* wp = (const double2*)(w2 + jt * 32 + ty * 8);
            double2 wa = wp[0], wb = wp[1], wc = wp[2], wd = wp[3];
            unsigned long long wr[8];
            wr[0] = __double_as_longlong(wa.x); wr[1] = __double_as_longlong(wa.y);
            wr[2] = __double_as_longlong(wb.x); wr[3] = __double_as_longlong(wb.y);
            wr[4] = __double_as_longlong(wc.x); wr[5] = __double_as_longlong(wc.y);
            wr[6] = __double_as_longlong(wd.x); wr[7] = __double_as_longlong(wd.y);
#pragma unroll
            for (int r = 0; r < 8; r++) {
                acc[r][0] = f2fma(wr[r], v01, acc[r][0]);
                acc[r][1] = f2fma(wr[r], v23, acc[r][1]);
            }
        }
        __syncthreads();
    }

    // epilogue: elu + store
#pragma unroll
    for (int r = 0; r < 8; r++) {
        int i = i0 + ty * 8 + r;
        int c = tx * 4;
        float o0 = lof(acc[r][0]);
        float o1 = hif(acc[r][0]);
        float o2 = lof(acc[r][1]);
        float o3 = hif(acc[r][1]);
        float4 o;
        o.x = o0 > 0.f ? o0 : (__expf(o0) - 1.f);
        o.y = o1 > 0.f ? o1 : (__expf(o1) - 1.f);
        o.z = o2 > 0.f ? o2 : (__expf(o2) - 1.f);
        o.w = o3 > 0.f ? o3 : (__expf(o3) - 1.f);
        *(float4*)(out + (size_t)i * FOUT + c) = o;
    }
}

// ---------------- launch -----------------------------------------------------
extern "C" void kernel_launch(void* const* d_in, const int* in_sizes, int n_in,
                              void* d_out, int out_size) {
    const int* adj = (const int*)d_in[0];
    const float* h = (const float*)d_in[1];
    const float* Wm = (const float*)d_in[2];
    const float* b = (const float*)d_in[3];
    const float* a1 = (const float*)d_in[4];
    const float* a2 = (const float*)d_in[5];
    const float* ab = (const float*)d_in[6];
    float* out = (float*)d_out;

    static bool attr_set = false;
    if (!attr_set) {
        cudaFuncSetAttribute(k_attn, cudaFuncAttributeMaxDynamicSharedMemorySize,
                             65536 + 16384 + 4096);
        attr_set = true;
    }

    k_gemm_wh<<<dim3(N / 64, FOUT / 64), 256>>>(h, Wm, b);
    k_fsd<<<N / 8, 256>>>(a1, a2, ab);
    k_prep<<<N, 128>>>(adj);
    k_attn<<<N / 32, 256, 65536 + 16384 + 4096>>>(out);
}

// round 2
// speedup vs baseline: 1.0035x; 1.0035x over previous
#include <cuda_runtime.h>
#include <cuda_bf16.h>

#define N 4096
#define FIN 512
#define FOUT 256
#define ALPHA 0.2f

// ---------------- scratch (device globals; no allocations allowed) ----------
__device__ float g_wh[N * FOUT];          // 4 MB  projected features
__device__ float g_fsrc[N];               // wh @ a1 + a_b
__device__ float g_fdst[N];               // wh @ a2
__device__ float g_mi[N];                 // row max logit
__device__ float g_rz[N];                 // 1 / Z_i
__device__ unsigned g_mask[N * (N / 32)]; // bit-packed adj, 2 MB

// ---------------- f32x2 packed-FMA helpers (sm_103a) ------------------------
__device__ __forceinline__ unsigned long long pk(float lo, float hi) {
    unsigned long long r;
    asm("mov.b64 %0, {%1,%2};" : "=l"(r) : "f"(lo), "f"(hi));
    return r;
}
__device__ __forceinline__ unsigned long long f2fma(unsigned long long a,
                                                    unsigned long long b,
                                                    unsigned long long c) {
    unsigned long long d;
    asm("fma.rn.f32x2 %0, %1, %2, %3;" : "=l"(d) : "l"(a), "l"(b), "l"(c));
    return d;
}
__device__ __forceinline__ float lof(unsigned long long v) {
    return __uint_as_float((unsigned)v);
}
__device__ __forceinline__ float hif(unsigned long long v) {
    return __uint_as_float((unsigned)(v >> 32));
}

// ---------------- kernel 1: wh = h @ W + b  (4096x512x256, fp32/f32x2) ------
// block 256 thr, tile 64(M) x 64(N), BK=32; each thread 4x4 via 2x f32x2 cols
__global__ __launch_bounds__(256) void k_gemm_wh(const float* __restrict__ h,
                                                 const float* __restrict__ Wm,
                                                 const float* __restrict__ bias) {
    __shared__ float As[64][33];  // h tile  [m][k], padded
    __shared__ float Bs[32][64];  // W tile  [k][n]

    const int t = threadIdx.x;
    const int m0 = blockIdx.x * 64;
    const int n0 = blockIdx.y * 64;
    const int tx = t & 15;   // 16 col groups of 4
    const int ty = t >> 4;   // 16 row groups of 4

    unsigned long long acc2[4][2];
#pragma unroll
    for (int i = 0; i < 4; i++) { acc2[i][0] = 0ull; acc2[i][1] = 0ull; }

    for (int k0 = 0; k0 < FIN; k0 += 32) {
        // load A tile: 64x32 = 512 float4
#pragma unroll
        for (int u = 0; u < 2; u++) {
            int idx = t + u * 256;
            int r = idx >> 3, c = (idx & 7) * 4;
            float4 v = *(const float4*)(h + (size_t)(m0 + r) * FIN + k0 + c);
            As[r][c] = v.x; As[r][c + 1] = v.y; As[r][c + 2] = v.z; As[r][c + 3] = v.w;
        }
        // load B tile: 32x64 = 512 float4
#pragma unroll
        for (int u = 0; u < 2; u++) {
            int idx = t + u * 256;
            int r = idx >> 4, c = (idx & 15) * 4;
            *(float4*)(&Bs[r][c]) = *(const float4*)(Wm + (size_t)(k0 + r) * FOUT + n0 + c);
        }
        __syncthreads();

#pragma unroll
        for (int k = 0; k < 32; k++) {
            double2 bd = *(const double2*)(&Bs[k][tx * 4]);
            unsigned long long b01 = __double_as_longlong(bd.x);
            unsigned long long b23 = __double_as_longlong(bd.y);
#pragma unroll
            for (int i = 0; i < 4; i++) {
                float a = As[ty * 4 + i][k];
                unsigned long long ap = pk(a, a);
                acc2[i][0] = f2fma(ap, b01, acc2[i][0]);
                acc2[i][1] = f2fma(ap, b23, acc2[i][1]);
            }
        }
        __syncthreads();
    }

    const int n = n0 + tx * 4;
    float4 bv = *(const float4*)(bias + n);
#pragma unroll
    for (int i = 0; i < 4; i++) {
        float4 o;
        o.x = lof(acc2[i][0]) + bv.x;
        o.y = hif(acc2[i][0]) + bv.y;
        o.z = lof(acc2[i][1]) + bv.z;
        o.w = hif(acc2[i][1]) + bv.w;
        *(float4*)(g_wh + (size_t)(m0 + ty * 4 + i) * FOUT + n) = o;
    }
}

// ---------------- kernel 2: f_src / f_dst (one warp per row) ----------------
__global__ __launch_bounds__(256) void k_fsd(const float* __restrict__ a1,
                                             const float* __restrict__ a2,
                                             const float* __restrict__ ab) {
    const int warp = threadIdx.x >> 5, lane = threadIdx.x & 31;
    const int i = blockIdx.x * 8 + warp;
    const float4* row = (const float4*)(g_wh + (size_t)i * FOUT);
    const float4* A1 = (const float4*)a1;
    const float4* A2 = (const float4*)a2;
    float s1 = 0.f, s2 = 0.f;
#pragma unroll
    for (int u = 0; u < 2; u++) {
        float4 v = row[lane + u * 32];
        float4 x = A1[lane + u * 32];
        float4 y = A2[lane + u * 32];
        s1 += v.x * x.x + v.y * x.y + v.z * x.z + v.w * x.w;
        s2 += v.x * y.x + v.y * y.y + v.z * y.z + v.w * y.w;
    }
#pragma unroll
    for (int o = 16; o; o >>= 1) {
        s1 += __shfl_down_sync(0xffffffffu, s1, o);
        s2 += __shfl_down_sync(0xffffffffu, s2, o);
    }
    if (lane == 0) {
        g_fsrc[i] = s1 + ab[0];  // fold a_b into f_src
        g_fdst[i] = s2;
    }
}

// ---------------- kernel 3: per-row softmax stats + adj bit-pack ------------
// one block (128 thr) per row. Reads adj exactly once (64 MB total).
__global__ __launch_bounds__(128) void k_prep(const int* __restrict__ adj) {
    const int i = blockIdx.x;
    const int t = threadIdx.x;
    const int warp = t >> 5, lane = t & 31;
    const float fs = g_fsrc[i];

    float fd[32];
    unsigned mybits = 0u;
    float mx = -3.4e38f;
    const int* arow = adj + (size_t)i * N;
#pragma unroll
    for (int m = 0; m < 32; m++) {
        int j = m * 128 + t;
        int a = arow[j];
        bool bit = a > 0;
        unsigned word = __ballot_sync(0xffffffffu, bit);
        if (lane == 0) g_mask[(size_t)i * 128 + m * 4 + warp] = word;
        float f = g_fdst[j];
        fd[m] = f;
        if (bit) { mx = fmaxf(mx, f); mybits |= (1u << m); }
    }

    __shared__ float red[128];
    red[t] = mx;
    __syncthreads();
#pragma unroll
    for (int s = 64; s > 0; s >>= 1) {
        if (t < s) red[t] = fmaxf(red[t], red[t + s]);
        __syncthreads();
    }
    float mxall = red[0];
    __syncthreads();

    float xm = fs + mxall;
    float mi = fmaxf(xm, ALPHA * xm);  // leaky_relu (monotone => row max logit)

    float s = 0.f;
#pragma unroll
    for (int m = 0; m < 32; m++) {
        if ((mybits >> m) & 1u) {
            float x = fs + fd[m];
            float l = fmaxf(x, ALPHA * x);
            s += __expf(l - mi);
        }
    }
    red[t] = s;
    __syncthreads();
#pragma unroll
    for (int sN = 64; sN > 0; sN >>= 1) {
        if (t < sN) red[t] += red[t + sN];
        __syncthreads();
    }
    if (t == 0) {
        g_mi[i] = mi;
        g_rz[i] = (red[0] > 0.f) ? (1.f / red[0]) : 0.f;
    }
}

// ---------------- kernel 4: fused attention-weighted GEMM + elu -------------
// grid 128 blocks, 256 thr. Block tile: 32(I) x 256(D), loop J in tiles of 64.
// dynamic smem: wh tile 64KB + packed-w 16KB + small.
__global__ __launch_bounds__(256) void k_attn(float* __restrict__ out) {
    extern __shared__ char smem[];
    float* wh_s = (float*)smem;                                    // 64*256 f32 = 64KB
    unsigned long long* w2 = (unsigned long long*)(smem + 65536);  // 64*32 u64 = 16KB
    float* fd_s = (float*)(smem + 65536 + 16384);                  // 64
    float* fs_s = fd_s + 64;                                       // 32
    float* mi_s = fs_s + 32;                                       // 32
    float* rz_s = mi_s + 32;                                       // 32
    unsigned* mw_s = (unsigned*)(rz_s + 32);                       // 64

    const int t = threadIdx.x;
    const int i0 = blockIdx.x * 32;

    if (t < 32) {
        fs_s[t] = g_fsrc[i0 + t];
        mi_s[t] = g_mi[i0 + t];
        rz_s[t] = g_rz[i0 + t];
    }

    unsigned long long acc[8][2];
#pragma unroll
    for (int r = 0; r < 8; r++) { acc[r][0] = 0ull; acc[r][1] = 0ull; }

    const int tx = t & 63;   // 64 col groups of 4 (D)
    const int ty = t >> 6;   // 4 row groups of 8 (I)

    __syncthreads();

    for (int j0 = 0; j0 < N; j0 += 64) {
        // load wh tile [64][256] : 4096 float4 / 256 thr = 16 each
        const float4* src = (const float4*)(g_wh + (size_t)j0 * FOUT);
        float4* dst = (float4*)wh_s;
#pragma unroll
        for (int k = 0; k < 16; k++) dst[t + 256 * k] = src[t + 256 * k];
        if (t < 64) fd_s[t] = g_fdst[j0 + t];
        if (t < 64) mw_s[t] = g_mask[(size_t)(i0 + (t >> 1)) * 128 + (j0 >> 5) + (t & 1)];
        __syncthreads();

        // phase 1: compute packed weights w2[jt][r] = (w,w)
        {
            const int r = t & 31, jg = t >> 5;
            const float fs = fs_s[r], mi = mi_s[r], rz = rz_s[r];
            const unsigned w0 = mw_s[r * 2], w1 = mw_s[r * 2 + 1];
            const unsigned wsel = (jg < 4) ? w0 : w1;
#pragma unroll
            for (int k2 = 0; k2 < 8; k2++) {
                int jt = jg * 8 + k2;
                unsigned bit = (wsel >> (jt & 31)) & 1u;
                float x = fs + fd_s[jt];
                float l = fmaxf(x, ALPHA * x);
                float wv = bit ? (__expf(l - mi) * rz) : 0.f;
                w2[jt * 32 + r] = pk(wv, wv);
            }
        }
        __syncthreads();

        // phase 2: acc[32x256] += w[32x64] * wh[64x256]  (packed f32x2 FMA)
#pragma unroll 8
        for (int jt = 0; jt < 64; jt++) {
            double2 vd = *(const double2*)(wh_s + jt * 256 + tx * 4);
            unsigned long long v01 = __double_as_longlong(vd.x);
            unsigned long long v23 = __double_as_longlong(vd.y);
            const double2* wp = (const double2*)(w2 + jt * 32 + ty * 8);
            double2 wa = wp[0], wb = wp[1], wc = wp[2], wd = wp[3];
            unsigned long long wr[8];
            wr[0] = __double_as_longlong(wa.x); wr[1] = __double_as_longlong(wa.y);
            wr[2] = __double_as_longlong(wb.x); wr[3] = __double_as_longlong(wb.y);
            wr[4] = __double_as_longlong(wc.x); wr[5] = __double_as_longlong(wc.y);
            wr[6] = __double_as_longlong(wd.x); wr[7] = __double_as_longlong(wd.y);
#pragma unroll
            for (int r = 0; r < 8; r++) {
                acc[r][0] = f2fma(wr[r], v01, acc[r][0]);
                acc[r][1] = f2fma(wr[r], v23, acc[r][1]);
            }
        }
        __syncthreads();
    }

    // epilogue: elu + store
#pragma unroll
    for (int r = 0; r < 8; r++) {
        int i = i0 + ty * 8 + r;
        int c = tx * 4;
        float o0 = lof(acc[r][0]);
        float o1 = hif(acc[r][0]);
        float o2 = lof(acc[r][1]);
        float o3 = hif(acc[r][1]);
        float4 o;
        o.x = o0 > 0.f ? o0 : (__expf(o0) - 1.f);
        o.y = o1 > 0.f ? o1 : (__expf(o1) - 1.f);
        o.z = o2 > 0.f ? o2 : (__expf(o2) - 1.f);
        o.w = o3 > 0.f ? o3 : (__expf(o3) - 1.f);
        *(float4*)(out + (size_t)i * FOUT + c) = o;
    }
}

// ---------------- launch -----------------------------------------------------
extern "C" void kernel_launch(void* const* d_in, const int* in_sizes, int n_in,
                              void* d_out, int out_size) {
    const int* adj = (const int*)d_in[0];
    const float* h = (const float*)d_in[1];
    const float* Wm = (const float*)d_in[2];
    const float* b = (const float*)d_in[3];
    const float* a1 = (const float*)d_in[4];
    const float* a2 = (const float*)d_in[5];
    const float* ab = (const float*)d_in[6];
    float* out = (float*)d_out;

    static bool attr_set = false;
    if (!attr_set) {
        cudaFuncSetAttribute(k_attn, cudaFuncAttributeMaxDynamicSharedMemorySize,
                             65536 + 16384 + 4096);
        attr_set = true;
    }

    k_gemm_wh<<<dim3(N / 64, FOUT / 64), 256>>>(h, Wm, b);
    k_fsd<<<N / 8, 256>>>(a1, a2, ab);
    k_prep<<<N, 128>>>(adj);
    k_attn<<<N / 32, 256, 65536 + 16384 + 4096>>>(out);
}

// round 4
// speedup vs baseline: 2.0949x; 2.0875x over previous
#include <cuda_runtime.h>
#include <cuda_bf16.h>
#include <cstdint>

#define N 4096
#define FIN 512
#define FOUT 256
#define ALPHA 0.2f
#define JSPLIT 2
#define KCTA (N / JSPLIT)   // 2048
#define NCHUNK (KCTA / 64)  // 32

// ---------------- device scratch ----------------
__device__ float g_wh[N * FOUT];
__device__ float g_fsrc[N];
__device__ float g_fdst[N];
__device__ float g_mi[N];
__device__ float g_rz[N];
__device__ unsigned g_mask[N * (N / 32)];                    // 2 MB
__device__ __align__(16) __nv_bfloat16 g_wh_hi[N * FOUT];    // 2 MB [j][d]
__device__ __align__(16) __nv_bfloat16 g_wh_lo[N * FOUT];    // 2 MB
__device__ __align__(16) float g_part[(size_t)JSPLIT * N * FOUT];  // 8 MB

// ---------------- base-ISA PTX helpers (valid on plain sm_103) --------------
__device__ __forceinline__ uint32_t smem_u32(const void* p) {
    uint32_t a;
    asm("{ .reg .u64 t; cvta.to.shared.u64 t, %1; cvt.u32.u64 %0, t; }" : "=r"(a) : "l"(p));
    return a;
}
__device__ __forceinline__ void ldm_x4(uint32_t* r, uint32_t addr) {
    asm volatile("ldmatrix.sync.aligned.m8n8.x4.shared.b16 {%0,%1,%2,%3}, [%4];"
                 : "=r"(r[0]), "=r"(r[1]), "=r"(r[2]), "=r"(r[3]) : "r"(addr));
}
__device__ __forceinline__ void ldm_x4_t(uint32_t* r, uint32_t addr) {
    asm volatile("ldmatrix.sync.aligned.m8n8.x4.trans.shared.b16 {%0,%1,%2,%3}, [%4];"
                 : "=r"(r[0]), "=r"(r[1]), "=r"(r[2]), "=r"(r[3]) : "r"(addr));
}
__device__ __forceinline__ void mma_bf16(float* c, const uint32_t* a, const uint32_t* b) {
    asm volatile(
        "mma.sync.aligned.m16n8k16.row.col.f32.bf16.bf16.f32 "
        "{%0,%1,%2,%3}, {%4,%5,%6,%7}, {%8,%9}, {%0,%1,%2,%3};"
        : "+f"(c[0]), "+f"(c[1]), "+f"(c[2]), "+f"(c[3])
        : "r"(a[0]), "r"(a[1]), "r"(a[2]), "r"(a[3]), "r"(b[0]), "r"(b[1]));
}
#define CP_ASYNC16(dst, src) \
    asm volatile("cp.async.cg.shared.global [%0], [%1], 16;" :: "r"(dst), "l"(src))
#define CP_COMMIT() asm volatile("cp.async.commit_group;" ::: "memory")
#define CP_WAIT0() asm volatile("cp.async.wait_group 0;" ::: "memory")

// ---------------- f32x2 helpers ----------------
__device__ __forceinline__ unsigned long long pk(float lo, float hi) {
    unsigned long long r;
    asm("mov.b64 %0, {%1,%2};" : "=l"(r) : "f"(lo), "f"(hi));
    return r;
}
__device__ __forceinline__ unsigned long long f2fma(unsigned long long a,
                                                    unsigned long long b,
                                                    unsigned long long c) {
    unsigned long long d;
    asm("fma.rn.f32x2 %0, %1, %2, %3;" : "=l"(d) : "l"(a), "l"(b), "l"(c));
    return d;
}
__device__ __forceinline__ float lof(unsigned long long v) { return __uint_as_float((unsigned)v); }
__device__ __forceinline__ float hif(unsigned long long v) { return __uint_as_float((unsigned)(v >> 32)); }

// ---------------- kernel 1: wh = h @ W + b, plus bf16 hi/lo split ------------
__global__ __launch_bounds__(256) void k_gemm_wh(const float* __restrict__ h,
                                                 const float* __restrict__ Wm,
                                                 const float* __restrict__ bias) {
    __shared__ float As[64][33];
    __shared__ float Bs[32][64];
    const int t = threadIdx.x;
    const int m0 = blockIdx.x * 64, n0 = blockIdx.y * 64;
    const int tx = t & 15, ty = t >> 4;
    unsigned long long acc2[4][2];
#pragma unroll
    for (int i = 0; i < 4; i++) { acc2[i][0] = 0ull; acc2[i][1] = 0ull; }
    for (int k0 = 0; k0 < FIN; k0 += 32) {
#pragma unroll
        for (int u = 0; u < 2; u++) {
            int idx = t + u * 256, r = idx >> 3, c = (idx & 7) * 4;
            float4 v = *(const float4*)(h + (size_t)(m0 + r) * FIN + k0 + c);
            As[r][c] = v.x; As[r][c + 1] = v.y; As[r][c + 2] = v.z; As[r][c + 3] = v.w;
        }
#pragma unroll
        for (int u = 0; u < 2; u++) {
            int idx = t + u * 256, r = idx >> 4, c = (idx & 15) * 4;
            *(float4*)(&Bs[r][c]) = *(const float4*)(Wm + (size_t)(k0 + r) * FOUT + n0 + c);
        }
        __syncthreads();
#pragma unroll
        for (int k = 0; k < 32; k++) {
            double2 bd = *(const double2*)(&Bs[k][tx * 4]);
            unsigned long long b01 = __double_as_longlong(bd.x);
            unsigned long long b23 = __double_as_longlong(bd.y);
#pragma unroll
            for (int i = 0; i < 4; i++) {
                float a = As[ty * 4 + i][k];
                unsigned long long ap = pk(a, a);
                acc2[i][0] = f2fma(ap, b01, acc2[i][0]);
                acc2[i][1] = f2fma(ap, b23, acc2[i][1]);
            }
        }
        __syncthreads();
    }
    const int n = n0 + tx * 4;
    float4 bv = *(const float4*)(bias + n);
#pragma unroll
    for (int i = 0; i < 4; i++) {
        float4 o;
        o.x = lof(acc2[i][0]) + bv.x; o.y = hif(acc2[i][0]) + bv.y;
        o.z = lof(acc2[i][1]) + bv.z; o.w = hif(acc2[i][1]) + bv.w;
        size_t gi = (size_t)(m0 + ty * 4 + i) * FOUT + n;
        *(float4*)(g_wh + gi) = o;
        __nv_bfloat162 ha = __floats2bfloat162_rn(o.x, o.y);
        __nv_bfloat162 hb = __floats2bfloat162_rn(o.z, o.w);
        __nv_bfloat162 la = __floats2bfloat162_rn(o.x - __bfloat162float(ha.x),
                                                  o.y - __bfloat162float(ha.y));
        __nv_bfloat162 lb = __floats2bfloat162_rn(o.z - __bfloat162float(hb.x),
                                                  o.w - __bfloat162float(hb.y));
        *(uint2*)(g_wh_hi + gi) = make_uint2(*(unsigned*)&ha, *(unsigned*)&hb);
        *(uint2*)(g_wh_lo + gi) = make_uint2(*(unsigned*)&la, *(unsigned*)&lb);
    }
}

// ---------------- kernel 2: f_src / f_dst ----------------
__global__ __launch_bounds__(256) void k_fsd(const float* __restrict__ a1,
                                             const float* __restrict__ a2,
                                             const float* __restrict__ ab) {
    const int warp = threadIdx.x >> 5, lane = threadIdx.x & 31;
    const int i = blockIdx.x * 8 + warp;
    const float4* row = (const float4*)(g_wh + (size_t)i * FOUT);
    const float4* A1 = (const float4*)a1;
    const float4* A2 = (const float4*)a2;
    float s1 = 0.f, s2 = 0.f;
#pragma unroll
    for (int u = 0; u < 2; u++) {
        float4 v = row[lane + u * 32], x = A1[lane + u * 32], y = A2[lane + u * 32];
        s1 += v.x * x.x + v.y * x.y + v.z * x.z + v.w * x.w;
        s2 += v.x * y.x + v.y * y.y + v.z * y.z + v.w * y.w;
    }
#pragma unroll
    for (int o = 16; o; o >>= 1) {
        s1 += __shfl_down_sync(0xffffffffu, s1, o);
        s2 += __shfl_down_sync(0xffffffffu, s2, o);
    }
    if (lane == 0) { g_fsrc[i] = s1 + ab[0]; g_fdst[i] = s2; }
}

// ---------------- kernel 3: softmax stats + bit-pack ----------------
__global__ __launch_bounds__(128) void k_prep(const int* __restrict__ adj) {
    const int i = blockIdx.x, t = threadIdx.x;
    const int warp = t >> 5, lane = t & 31;
    const float fs = g_fsrc[i];
    float fd[32];
    unsigned mybits = 0u;
    float mx = -3.4e38f;
    const int* arow = adj + (size_t)i * N;
#pragma unroll
    for (int m = 0; m < 32; m++) {
        int j = m * 128 + t;
        bool bit = arow[j] > 0;
        unsigned word = __ballot_sync(0xffffffffu, bit);
        if (lane == 0) g_mask[(size_t)i * 128 + m * 4 + warp] = word;
        float f = g_fdst[j];
        fd[m] = f;
        if (bit) { mx = fmaxf(mx, f); mybits |= (1u << m); }
    }
    __shared__ float red[128];
    red[t] = mx;
    __syncthreads();
#pragma unroll
    for (int s = 64; s > 0; s >>= 1) {
        if (t < s) red[t] = fmaxf(red[t], red[t + s]);
        __syncthreads();
    }
    float xm = fs + red[0];
    __syncthreads();
    float mi = fmaxf(xm, ALPHA * xm);
    float s = 0.f;
#pragma unroll
    for (int m = 0; m < 32; m++)
        if ((mybits >> m) & 1u) {
            float x = fs + fd[m];
            s += __expf(fmaxf(x, ALPHA * x) - mi);
        }
    red[t] = s;
    __syncthreads();
#pragma unroll
    for (int sN = 64; sN > 0; sN >>= 1) {
        if (t < sN) red[t] += red[t + sN];
        __syncthreads();
    }
    if (t == 0) { g_mi[i] = mi; g_rz[i] = (red[0] > 0.f) ? (1.f / red[0]) : 0.f; }
}

// ---------------- kernel 4: HMMA attention GEMM (compensated bf16) ----------
// grid (64 i-tiles, 2 j-splits), 256 thr. M=64, N=256, K=2048 in 32 chunks of 64.
// smem: fd 8KB | mask 16KB | 2 stages x 84KB {A_hi 9216 | A_lo 9216 | B_hi 33792 | B_lo 33792}
#define SM_FD 0
#define SM_MASK 8192
#define SM_STG0 24576
#define A_HI 0
#define A_LO 9216
#define B_HI 18432
#define B_LO 52224
#define STG 86016
#define SMEM_AT (SM_STG0 + 2 * STG)  // 196608

__global__ __launch_bounds__(256, 1) void k_attn_h() {
    extern __shared__ char smem[];
    const uint32_t sbase = smem_u32(smem);
    float* fd_s = (float*)(smem + SM_FD);
    unsigned* mask_s = (unsigned*)(smem + SM_MASK);
    const int t = threadIdx.x;
    const int lane = t & 31, warp = t >> 5;
    const int i0 = blockIdx.x * 64;
    const int js = blockIdx.y;
    const int jorg = js * KCTA;

    // per-thread A-gen constants: this thread always generates row i = t>>2
    const int gi = i0 + (t >> 2);
    const float fsi = g_fsrc[gi];
    const float mii = g_mi[gi];
    const float rzi = g_rz[gi];

    // preload fd (2048 f) + mask (64 rows x 64 words)
#pragma unroll
    for (int u = 0; u < 2; u++) {
        int idx = t + 256 * u;
        *(float4*)(fd_s + idx * 4) = *(const float4*)(g_fdst + jorg + idx * 4);
    }
#pragma unroll
    for (int u = 0; u < 16; u++) {
        int idx = t + 256 * u;
        mask_s[idx] = g_mask[(size_t)(i0 + (idx >> 6)) * 128 + js * 64 + (idx & 63)];
    }
    __syncthreads();

    // ---- stage fill helpers ----
    auto fill_B = [&](int c2, uint32_t stg_s) {
        size_t jg = (size_t)jorg + (size_t)c2 * 64;
#pragma unroll
        for (int u = 0; u < 8; u++) {
            int idx = t + 256 * u;
            int j = idx >> 5, dq = idx & 31;
            uint32_t dst = stg_s + B_HI + j * 528 + dq * 16;
            size_t src = (jg + j) * FOUT + dq * 8;
            CP_ASYNC16(dst, (const void*)(g_wh_hi + src));
            CP_ASYNC16(dst + (B_LO - B_HI), (const void*)(g_wh_lo + src));
        }
    };
    auto fill_A = [&](int c2, char* stgp) {
        unsigned w = mask_s[(t >> 2) * 64 + c2 * 2 + ((t & 3) >> 1)];
        const int shift = (t & 1) * 16;
        const float* fdp = fd_s + c2 * 64 + (t & 3) * 16;
        uint32_t hv[8], lv[8];
#pragma unroll
        for (int v = 0; v < 16; v += 2) {
            float e0 = 0.f, e1 = 0.f;
            if ((w >> (shift + v)) & 1u) {
                float x = fsi + fdp[v];
                e0 = __expf(fmaxf(x, ALPHA * x) - mii) * rzi;
            }
            if ((w >> (shift + v + 1)) & 1u) {
                float x = fsi + fdp[v + 1];
                e1 = __expf(fmaxf(x, ALPHA * x) - mii) * rzi;
            }
            __nv_bfloat162 h2 = __floats2bfloat162_rn(e0, e1);
            __nv_bfloat162 l2 = __floats2bfloat162_rn(e0 - __bfloat162float(h2.x),
                                                      e1 - __bfloat162float(h2.y));
            hv[v >> 1] = *(uint32_t*)&h2;
            lv[v >> 1] = *(uint32_t*)&l2;
        }
        char* pA = stgp + (t >> 2) * 144 + (t & 3) * 32;
        *(uint4*)(pA + A_HI) = make_uint4(hv[0], hv[1], hv[2], hv[3]);
        *(uint4*)(pA + A_HI + 16) = make_uint4(hv[4], hv[5], hv[6], hv[7]);
        *(uint4*)(pA + A_LO) = make_uint4(lv[0], lv[1], lv[2], lv[3]);
        *(uint4*)(pA + A_LO + 16) = make_uint4(lv[4], lv[5], lv[6], lv[7]);
    };

    float acc[4][4][4];
#pragma unroll
    for (int a = 0; a < 4; a++)
#pragma unroll
        for (int b = 0; b < 4; b++)
#pragma unroll
            for (int c = 0; c < 4; c++) acc[a][b][c] = 0.f;

    // ldmatrix address bases (per-thread, constant across chunks)
    const uint32_t a_off = (lane & 15) * 144 + ((lane >> 4) * 8) * 2;
    const uint32_t b_off = (lane & 15) * 528 + (warp * 32 + (lane >> 4) * 8) * 2;

    // prolog: fill chunk 0 into stage 0
    fill_B(0, sbase + SM_STG0);
    CP_COMMIT();
    fill_A(0, smem + SM_STG0);
    CP_WAIT0();
    __syncthreads();

    for (int c = 0; c < NCHUNK; c++) {
        const int s = c & 1;
        const uint32_t stg = SM_STG0 + (uint32_t)s * STG;
        const uint32_t stg2 = SM_STG0 + (uint32_t)(s ^ 1) * STG;
        if (c + 1 < NCHUNK) { fill_B(c + 1, sbase + stg2); CP_COMMIT(); }

        const uint32_t Ah = sbase + stg + A_HI;
        const uint32_t Al = sbase + stg + A_LO;
        const uint32_t Bh = sbase + stg + B_HI;
        const uint32_t Bl = sbase + stg + B_LO;
#pragma unroll
        for (int kk = 0; kk < 4; kk++) {
            uint32_t ah[4][4], al[4][4], bh[2][4], bl[2][4];
            const uint32_t ao = a_off + kk * 32;
            const uint32_t bo = b_off + kk * 16 * 528;
#pragma unroll
            for (int mt = 0; mt < 4; mt++) {
                ldm_x4(ah[mt], Ah + mt * 2304 + ao);
                ldm_x4(al[mt], Al + mt * 2304 + ao);
            }
            ldm_x4_t(bh[0], Bh + bo);
            ldm_x4_t(bh[1], Bh + bo + 32);
            ldm_x4_t(bl[0], Bl + bo);
            ldm_x4_t(bl[1], Bl + bo + 32);
#pragma unroll
            for (int mt = 0; mt < 4; mt++)
#pragma unroll
                for (int nb = 0; nb < 4; nb++) {
                    const uint32_t* bfh = &bh[nb >> 1][(nb & 1) * 2];
                    const uint32_t* bfl = &bl[nb >> 1][(nb & 1) * 2];
                    mma_bf16(acc[mt][nb], ah[mt], bfh);  // hi*hi
                    mma_bf16(acc[mt][nb], ah[mt], bfl);  // hi*lo
                    mma_bf16(acc[mt][nb], al[mt], bfh);  // lo*hi
                }
        }
        if (c + 1 < NCHUNK) fill_A(c + 1, smem + stg2);
        CP_WAIT0();
        __syncthreads();
    }

    // epilogue: write partials
    float* base = g_part + (size_t)js * ((size_t)N * FOUT);
#pragma unroll
    for (int mt = 0; mt < 4; mt++) {
        int ir = i0 + mt * 16 + (lane >> 2);
#pragma unroll
        for (int nb = 0; nb < 4; nb++) {
            int d = warp * 32 + nb * 8 + (lane & 3) * 2;
            *(float2*)(base + (size_t)ir * FOUT + d) =
                make_float2(acc[mt][nb][0], acc[mt][nb][1]);
            *(float2*)(base + (size_t)(ir + 8) * FOUT + d) =
                make_float2(acc[mt][nb][2], acc[mt][nb][3]);
        }
    }
}

// ---------------- kernel 5: combine partials + elu ----------------
__global__ __launch_bounds__(256) void k_comb(float* __restrict__ out) {
    const size_t idx = ((size_t)blockIdx.x * 256 + threadIdx.x) * 4;
    const size_t stride = (size_t)N * FOUT;
    float4 a = *(const float4*)(g_part + idx);
    float4 b = *(const float4*)(g_part + stride + idx);
    float4 o;
    o.x = a.x + b.x; o.y = a.y + b.y; o.z = a.z + b.z; o.w = a.w + b.w;
    o.x = o.x > 0.f ? o.x : (__expf(o.x) - 1.f);
    o.y = o.y > 0.f ? o.y : (__expf(o.y) - 1.f);
    o.z = o.z > 0.f ? o.z : (__expf(o.z) - 1.f);
    o.w = o.w > 0.f ? o.w : (__expf(o.w) - 1.f);
    *(float4*)(out + idx) = o;
}

// ---------------- launch ----------------
extern "C" void kernel_launch(void* const* d_in, const int* in_sizes, int n_in,
                              void* d_out, int out_size) {
    const int* adj = (const int*)d_in[0];
    const float* h = (const float*)d_in[1];
    const float* Wm = (const float*)d_in[2];
    const float* b = (const float*)d_in[3];
    const float* a1 = (const float*)d_in[4];
    const float* a2 = (const float*)d_in[5];
    const float* ab = (const float*)d_in[6];
    float* out = (float*)d_out;

    static bool attr_set = false;
    if (!attr_set) {
        cudaFuncSetAttribute(k_attn_h, cudaFuncAttributeMaxDynamicSharedMemorySize, SMEM_AT);
        attr_set = true;
    }

    k_gemm_wh<<<dim3(N / 64, FOUT / 64), 256>>>(h, Wm, b);
    k_fsd<<<N / 8, 256>>>(a1, a2, ab);
    k_prep<<<N, 128>>>(adj);
    k_attn_h<<<dim3(N / 64, JSPLIT), 256, SMEM_AT>>>();
    k_comb<<<(N * FOUT) / 1024, 256>>>(out);
}

// round 5
// speedup vs baseline: 2.1372x; 1.0202x over previous
#include <cuda_runtime.h>
#include <cuda_bf16.h>
#include <cstdint>

#define N 4096
#define FIN 512
#define FOUT 256
#define ALPHA 0.2f
#define JSPLIT 2
#define KCTA (N / JSPLIT)   // 2048
#define NCHUNK (KCTA / 64)  // 32

// ---------------- device scratch ----------------
__device__ float g_wh[N * FOUT];
__device__ float g_fsrc[N];
__device__ float g_fdst[N];
__device__ float g_mi[N];
__device__ float g_rz[N];
__device__ unsigned g_mask[N * (N / 32)];                    // 2 MB
__device__ __align__(16) __nv_bfloat16 g_wh_hi[N * FOUT];    // 2 MB [j][d]
__device__ __align__(16) __nv_bfloat16 g_wh_lo[N * FOUT];    // 2 MB
__device__ __align__(16) float g_part[(size_t)JSPLIT * N * FOUT];  // 8 MB

// ---------------- base-ISA PTX helpers ----------------
__device__ __forceinline__ uint32_t smem_u32(const void* p) {
    uint32_t a;
    asm("{ .reg .u64 t; cvta.to.shared.u64 t, %1; cvt.u32.u64 %0, t; }" : "=r"(a) : "l"(p));
    return a;
}
__device__ __forceinline__ void ldm_x4(uint32_t* r, uint32_t addr) {
    asm volatile("ldmatrix.sync.aligned.m8n8.x4.shared.b16 {%0,%1,%2,%3}, [%4];"
                 : "=r"(r[0]), "=r"(r[1]), "=r"(r[2]), "=r"(r[3]) : "r"(addr));
}
__device__ __forceinline__ void ldm_x4_t(uint32_t* r, uint32_t addr) {
    asm volatile("ldmatrix.sync.aligned.m8n8.x4.trans.shared.b16 {%0,%1,%2,%3}, [%4];"
                 : "=r"(r[0]), "=r"(r[1]), "=r"(r[2]), "=r"(r[3]) : "r"(addr));
}
__device__ __forceinline__ void mma_bf16(float* c, const uint32_t* a, const uint32_t* b) {
    asm volatile(
        "mma.sync.aligned.m16n8k16.row.col.f32.bf16.bf16.f32 "
        "{%0,%1,%2,%3}, {%4,%5,%6,%7}, {%8,%9}, {%0,%1,%2,%3};"
        : "+f"(c[0]), "+f"(c[1]), "+f"(c[2]), "+f"(c[3])
        : "r"(a[0]), "r"(a[1]), "r"(a[2]), "r"(a[3]), "r"(b[0]), "r"(b[1]));
}
#define CP_ASYNC16(dst, src) \
    asm volatile("cp.async.cg.shared.global [%0], [%1], 16;" :: "r"(dst), "l"(src))
#define CP_COMMIT() asm volatile("cp.async.commit_group;" ::: "memory")
#define CP_WAIT0() asm volatile("cp.async.wait_group 0;" ::: "memory")

// ---------------- f32x2 helpers ----------------
__device__ __forceinline__ unsigned long long pk(float lo, float hi) {
    unsigned long long r;
    asm("mov.b64 %0, {%1,%2};" : "=l"(r) : "f"(lo), "f"(hi));
    return r;
}
__device__ __forceinline__ unsigned long long f2fma(unsigned long long a,
                                                    unsigned long long b,
                                                    unsigned long long c) {
    unsigned long long d;
    asm("fma.rn.f32x2 %0, %1, %2, %3;" : "=l"(d) : "l"(a), "l"(b), "l"(c));
    return d;
}
__device__ __forceinline__ float lof(unsigned long long v) { return __uint_as_float((unsigned)v); }
__device__ __forceinline__ float hif(unsigned long long v) { return __uint_as_float((unsigned)(v >> 32)); }

// ---------------- kernel 1: wh = h @ W + b, plus bf16 hi/lo split ------------
__global__ __launch_bounds__(256) void k_gemm_wh(const float* __restrict__ h,
                                                 const float* __restrict__ Wm,
                                                 const float* __restrict__ bias) {
    __shared__ float As[64][33];
    __shared__ float Bs[32][64];
    const int t = threadIdx.x;
    const int m0 = blockIdx.x * 64, n0 = blockIdx.y * 64;
    const int tx = t & 15, ty = t >> 4;
    unsigned long long acc2[4][2];
#pragma unroll
    for (int i = 0; i < 4; i++) { acc2[i][0] = 0ull; acc2[i][1] = 0ull; }
    for (int k0 = 0; k0 < FIN; k0 += 32) {
#pragma unroll
        for (int u = 0; u < 2; u++) {
            int idx = t + u * 256, r = idx >> 3, c = (idx & 7) * 4;
            float4 v = *(const float4*)(h + (size_t)(m0 + r) * FIN + k0 + c);
            As[r][c] = v.x; As[r][c + 1] = v.y; As[r][c + 2] = v.z; As[r][c + 3] = v.w;
        }
#pragma unroll
        for (int u = 0; u < 2; u++) {
            int idx = t + u * 256, r = idx >> 4, c = (idx & 15) * 4;
            *(float4*)(&Bs[r][c]) = *(const float4*)(Wm + (size_t)(k0 + r) * FOUT + n0 + c);
        }
        __syncthreads();
#pragma unroll
        for (int k = 0; k < 32; k++) {
            double2 bd = *(const double2*)(&Bs[k][tx * 4]);
            unsigned long long b01 = __double_as_longlong(bd.x);
            unsigned long long b23 = __double_as_longlong(bd.y);
#pragma unroll
            for (int i = 0; i < 4; i++) {
                float a = As[ty * 4 + i][k];
                unsigned long long ap = pk(a, a);
                acc2[i][0] = f2fma(ap, b01, acc2[i][0]);
                acc2[i][1] = f2fma(ap, b23, acc2[i][1]);
            }
        }
        __syncthreads();
    }
    const int n = n0 + tx * 4;
    float4 bv = *(const float4*)(bias + n);
#pragma unroll
    for (int i = 0; i < 4; i++) {
        float4 o;
        o.x = lof(acc2[i][0]) + bv.x; o.y = hif(acc2[i][0]) + bv.y;
        o.z = lof(acc2[i][1]) + bv.z; o.w = hif(acc2[i][1]) + bv.w;
        size_t gi = (size_t)(m0 + ty * 4 + i) * FOUT + n;
        *(float4*)(g_wh + gi) = o;
        __nv_bfloat162 ha = __floats2bfloat162_rn(o.x, o.y);
        __nv_bfloat162 hb = __floats2bfloat162_rn(o.z, o.w);
        __nv_bfloat162 la = __floats2bfloat162_rn(o.x - __bfloat162float(ha.x),
                                                  o.y - __bfloat162float(ha.y));
        __nv_bfloat162 lb = __floats2bfloat162_rn(o.z - __bfloat162float(hb.x),
                                                  o.w - __bfloat162float(hb.y));
        *(uint2*)(g_wh_hi + gi) = make_uint2(*(unsigned*)&ha, *(unsigned*)&hb);
        *(uint2*)(g_wh_lo + gi) = make_uint2(*(unsigned*)&la, *(unsigned*)&lb);
    }
}

// ---------------- kernel 2: f_src / f_dst ----------------
__global__ __launch_bounds__(256) void k_fsd(const float* __restrict__ a1,
                                             const float* __restrict__ a2,
                                             const float* __restrict__ ab) {
    const int warp = threadIdx.x >> 5, lane = threadIdx.x & 31;
    const int i = blockIdx.x * 8 + warp;
    const float4* row = (const float4*)(g_wh + (size_t)i * FOUT);
    const float4* A1 = (const float4*)a1;
    const float4* A2 = (const float4*)a2;
    float s1 = 0.f, s2 = 0.f;
#pragma unroll
    for (int u = 0; u < 2; u++) {
        float4 v = row[lane + u * 32], x = A1[lane + u * 32], y = A2[lane + u * 32];
        s1 += v.x * x.x + v.y * x.y + v.z * x.z + v.w * x.w;
        s2 += v.x * y.x + v.y * y.y + v.z * y.z + v.w * y.w;
    }
#pragma unroll
    for (int o = 16; o; o >>= 1) {
        s1 += __shfl_down_sync(0xffffffffu, s1, o);
        s2 += __shfl_down_sync(0xffffffffu, s2, o);
    }
    if (lane == 0) { g_fsrc[i] = s1 + ab[0]; g_fdst[i] = s2; }
}

// ---------------- kernel 3: softmax stats + bit-pack (256 thr, int4) --------
__global__ __launch_bounds__(256) void k_prep(const int* __restrict__ adj) {
    const int i = blockIdx.x, t = threadIdx.x;
    const float fs = g_fsrc[i];
    const int4* arow = (const int4*)(adj + (size_t)i * N);

    float fdv[16];
    const float4* fdp = (const float4*)g_fdst;
#pragma unroll
    for (int v = 0; v < 4; v++) {
        float4 f = fdp[t * 4 + v];
        fdv[v * 4 + 0] = f.x; fdv[v * 4 + 1] = f.y;
        fdv[v * 4 + 2] = f.z; fdv[v * 4 + 3] = f.w;
    }
    unsigned bits = 0;
#pragma unroll
    for (int q = 0; q < 4; q++) {
        int4 a = arow[t * 4 + q];
        if (a.x > 0) bits |= 1u << (q * 4 + 0);
        if (a.y > 0) bits |= 1u << (q * 4 + 1);
        if (a.z > 0) bits |= 1u << (q * 4 + 2);
        if (a.w > 0) bits |= 1u << (q * 4 + 3);
    }
    unsigned other = __shfl_xor_sync(0xffffffffu, bits, 1);
    if ((t & 1) == 0) g_mask[(size_t)i * 128 + (t >> 1)] = bits | (other << 16);

    float mx = -3.4e38f;
#pragma unroll
    for (int v = 0; v < 16; v++)
        if ((bits >> v) & 1u) mx = fmaxf(mx, fdv[v]);
#pragma unroll
    for (int o = 16; o; o >>= 1) mx = fmaxf(mx, __shfl_xor_sync(0xffffffffu, mx, o));
    __shared__ float redm[8];
    __shared__ float reds[8];
    if ((t & 31) == 0) redm[t >> 5] = mx;
    __syncthreads();
    float mxall = redm[0];
#pragma unroll
    for (int w = 1; w < 8; w++) mxall = fmaxf(mxall, redm[w]);
    float xm = fs + mxall;
    float mi = fmaxf(xm, ALPHA * xm);

    float s = 0.f;
#pragma unroll
    for (int v = 0; v < 16; v++)
        if ((bits >> v) & 1u) {
            float x = fs + fdv[v];
            s += __expf(fmaxf(x, ALPHA * x) - mi);
        }
#pragma unroll
    for (int o = 16; o; o >>= 1) s += __shfl_xor_sync(0xffffffffu, s, o);
    if ((t & 31) == 0) reds[t >> 5] = s;
    __syncthreads();
    if (t == 0) {
        float stot = 0.f;
#pragma unroll
        for (int w = 0; w < 8; w++) stot += reds[w];
        g_mi[i] = mi;
        g_rz[i] = (stot > 0.f) ? (1.f / stot) : 0.f;
    }
}

// ---------------- kernel 4: HMMA attention GEMM, register-pipelined ----------
#define SM_FD 0
#define SM_MASK 8192
#define SM_STG0 24576
#define A_HI 0
#define A_LO 9216
#define B_HI 18432
#define B_LO 52224
#define STG 86016
#define SMEM_AT (SM_STG0 + 2 * STG)  // 196608

__global__ __launch_bounds__(256, 1) void k_attn_h() {
    extern __shared__ char smem[];
    const uint32_t sbase = smem_u32(smem);
    float* fd_s = (float*)(smem + SM_FD);
    unsigned* mask_s = (unsigned*)(smem + SM_MASK);
    const int t = threadIdx.x;
    const int lane = t & 31, warp = t >> 5;
    const int i0 = blockIdx.x * 64;
    const int js = blockIdx.y;
    const int jorg = js * KCTA;

    const int gi = i0 + (t >> 2);
    const float fsi = g_fsrc[gi];
    const float mii = g_mi[gi];
    const float rzi = g_rz[gi];

#pragma unroll
    for (int u = 0; u < 2; u++) {
        int idx = t + 256 * u;
        *(float4*)(fd_s + idx * 4) = *(const float4*)(g_fdst + jorg + idx * 4);
    }
#pragma unroll
    for (int u = 0; u < 16; u++) {
        int idx = t + 256 * u;
        mask_s[idx] = g_mask[(size_t)(i0 + (idx >> 6)) * 128 + js * 64 + (idx & 63)];
    }
    __syncthreads();

    auto fill_B = [&](int c2, uint32_t stg_s) {
        size_t jg = (size_t)jorg + (size_t)c2 * 64;
#pragma unroll
        for (int u = 0; u < 8; u++) {
            int idx = t + 256 * u;
            int j = idx >> 5, dq = idx & 31;
            uint32_t dst = stg_s + B_HI + j * 528 + dq * 16;
            size_t src = (jg + j) * FOUT + dq * 8;
            CP_ASYNC16(dst, (const void*)(g_wh_hi + src));
            CP_ASYNC16(dst + (B_LO - B_HI), (const void*)(g_wh_lo + src));
        }
    };
    auto fill_A = [&](int c2, char* stgp) {
        unsigned w = mask_s[(t >> 2) * 64 + c2 * 2 + ((t & 3) >> 1)];
        const int shift = (t & 1) * 16;
        const float* fdp = fd_s + c2 * 64 + (t & 3) * 16;
        uint32_t hv[8], lv[8];
#pragma unroll
        for (int v = 0; v < 16; v += 2) {
            float e0 = 0.f, e1 = 0.f;
            if ((w >> (shift + v)) & 1u) {
                float x = fsi + fdp[v];
                e0 = __expf(fmaxf(x, ALPHA * x) - mii) * rzi;
            }
            if ((w >> (shift + v + 1)) & 1u) {
                float x = fsi + fdp[v + 1];
                e1 = __expf(fmaxf(x, ALPHA * x) - mii) * rzi;
            }
            __nv_bfloat162 h2 = __floats2bfloat162_rn(e0, e1);
            __nv_bfloat162 l2 = __floats2bfloat162_rn(e0 - __bfloat162float(h2.x),
                                                      e1 - __bfloat162float(h2.y));
            hv[v >> 1] = *(uint32_t*)&h2;
            lv[v >> 1] = *(uint32_t*)&l2;
        }
        char* pA = stgp + (t >> 2) * 144 + (t & 3) * 32;
        *(uint4*)(pA + A_HI) = make_uint4(hv[0], hv[1], hv[2], hv[3]);
        *(uint4*)(pA + A_HI + 16) = make_uint4(hv[4], hv[5], hv[6], hv[7]);
        *(uint4*)(pA + A_LO) = make_uint4(lv[0], lv[1], lv[2], lv[3]);
        *(uint4*)(pA + A_LO + 16) = make_uint4(lv[4], lv[5], lv[6], lv[7]);
    };

    float acc[4][4][4];
#pragma unroll
    for (int a = 0; a < 4; a++)
#pragma unroll
        for (int b = 0; b < 4; b++)
#pragma unroll
            for (int c = 0; c < 4; c++) acc[a][b][c] = 0.f;

    const uint32_t a_off = (lane & 15) * 144 + ((lane >> 4) * 8) * 2;
    const uint32_t b_off = (lane & 15) * 528 + (warp * 32 + (lane >> 4) * 8) * 2;

    // double-buffered register fragments
    uint32_t ah[2][4][4], al[2][4][4], bh[2][2][4], bl[2][2][4];

    // prolog: fill chunk 0 into stage 0
    fill_B(0, sbase + SM_STG0);
    CP_COMMIT();
    fill_A(0, smem + SM_STG0);
    CP_WAIT0();
    __syncthreads();

#pragma unroll 1
    for (int c = 0; c < NCHUNK; c++) {
        const int s = c & 1;
        const uint32_t stg = SM_STG0 + (uint32_t)s * STG;
        const uint32_t stg2 = SM_STG0 + (uint32_t)(s ^ 1) * STG;
        const uint32_t Ah = sbase + stg + A_HI;
        const uint32_t Al = sbase + stg + A_LO;
        const uint32_t Bh = sbase + stg + B_HI;
        const uint32_t Bl = sbase + stg + B_LO;

        // load fragment set for a kk step into buffer `buf`
        auto load_frags = [&](int buf, int kk) {
            const uint32_t ao = a_off + kk * 32;
            const uint32_t bo = b_off + kk * 16 * 528;
#pragma unroll
            for (int mt = 0; mt < 4; mt++) {
                ldm_x4(ah[buf][mt], Ah + mt * 2304 + ao);
                ldm_x4(al[buf][mt], Al + mt * 2304 + ao);
            }
            ldm_x4_t(bh[buf][0], Bh + bo);
            ldm_x4_t(bh[buf][1], Bh + bo + 32);
            ldm_x4_t(bl[buf][0], Bl + bo);
            ldm_x4_t(bl[buf][1], Bl + bo + 32);
        };
        auto mma_all = [&](int buf) {
#pragma unroll
            for (int mt = 0; mt < 4; mt++)
#pragma unroll
                for (int nb = 0; nb < 4; nb++) {
                    const uint32_t* bfh = &bh[buf][nb >> 1][(nb & 1) * 2];
                    const uint32_t* bfl = &bl[buf][nb >> 1][(nb & 1) * 2];
                    mma_bf16(acc[mt][nb], ah[buf][mt], bfh);  // hi*hi
                    mma_bf16(acc[mt][nb], ah[buf][mt], bfl);  // hi*lo
                    mma_bf16(acc[mt][nb], al[buf][mt], bfh);  // lo*hi
                }
        };

        load_frags(0, 0);
        if (c + 1 < NCHUNK) { fill_B(c + 1, sbase + stg2); CP_COMMIT(); }
        load_frags(1, 1);
        mma_all(0);
        if (c + 1 < NCHUNK) fill_A(c + 1, smem + stg2);
        load_frags(0, 2);
        mma_all(1);
        load_frags(1, 3);
        mma_all(0);
        mma_all(1);

        CP_WAIT0();
        __syncthreads();
    }

    // epilogue: write partials
    float* base = g_part + (size_t)js * ((size_t)N * FOUT);
#pragma unroll
    for (int mt = 0; mt < 4; mt++) {
        int ir = i0 + mt * 16 + (lane >> 2);
#pragma unroll
        for (int nb = 0; nb < 4; nb++) {
            int d = warp * 32 + nb * 8 + (lane & 3) * 2;
            *(float2*)(base + (size_t)ir * FOUT + d) =
                make_float2(acc[mt][nb][0], acc[mt][nb][1]);
            *(float2*)(base + (size_t)(ir + 8) * FOUT + d) =
                make_float2(acc[mt][nb][2], acc[mt][nb][3]);
        }
    }
}

// ---------------- kernel 5: combine partials + elu ----------------
__global__ __launch_bounds__(256) void k_comb(float* __restrict__ out) {
    const size_t idx = ((size_t)blockIdx.x * 256 + threadIdx.x) * 4;
    const size_t stride = (size_t)N * FOUT;
    float4 a = *(const float4*)(g_part + idx);
    float4 b = *(const float4*)(g_part + stride + idx);
    float4 o;
    o.x = a.x + b.x; o.y = a.y + b.y; o.z = a.z + b.z; o.w = a.w + b.w;
    o.x = o.x > 0.f ? o.x : (__expf(o.x) - 1.f);
    o.y = o.y > 0.f ? o.y : (__expf(o.y) - 1.f);
    o.z = o.z > 0.f ? o.z : (__expf(o.z) - 1.f);
    o.w = o.w > 0.f ? o.w : (__expf(o.w) - 1.f);
    *(float4*)(out + idx) = o;
}

// ---------------- launch ----------------
extern "C" void kernel_launch(void* const* d_in, const int* in_sizes, int n_in,
                              void* d_out, int out_size) {
    const int* adj = (const int*)d_in[0];
    const float* h = (const float*)d_in[1];
    const float* Wm = (const float*)d_in[2];
    const float* b = (const float*)d_in[3];
    const float* a1 = (const float*)d_in[4];
    const float* a2 = (const float*)d_in[5];
    const float* ab = (const float*)d_in[6];
    float* out = (float*)d_out;

    static bool attr_set = false;
    if (!attr_set) {
        cudaFuncSetAttribute(k_attn_h, cudaFuncAttributeMaxDynamicSharedMemorySize, SMEM_AT);
        attr_set = true;
    }

    k_gemm_wh<<<dim3(N / 64, FOUT / 64), 256>>>(h, Wm, b);
    k_fsd<<<N / 8, 256>>>(a1, a2, ab);
    k_prep<<<N, 256>>>(adj);
    k_attn_h<<<dim3(N / 64, JSPLIT), 256, SMEM_AT>>>();
    k_comb<<<(N * FOUT) / 1024, 256>>>(out);
}

// round 6
// speedup vs baseline: 2.4392x; 1.1413x over previous
#include <cuda_runtime.h>
#include <cuda_bf16.h>
#include <cstdint>

#define N 4096
#define FIN 512
#define FOUT 256
#define ALPHA 0.2f
#define JSPLIT 2
#define KCTA (N / JSPLIT)   // 2048
#define NCHUNK (KCTA / 64)  // 32

// ---------------- device scratch ----------------
__device__ float g_wh[N * FOUT];
__device__ float g_fsrc[N];
__device__ float g_fdst[N];
__device__ float g_mi[N];
__device__ float g_rz[N];
__device__ unsigned g_mask[N * (N / 32)];                    // 2 MB
__device__ __align__(16) __nv_bfloat16 g_wh_hi[N * FOUT];    // 2 MB [j][d]
__device__ __align__(16) __nv_bfloat16 g_wh_lo[N * FOUT];    // 2 MB
__device__ __align__(16) float g_part[(size_t)JSPLIT * N * FOUT];  // 8 MB

// ---------------- base-ISA PTX helpers ----------------
__device__ __forceinline__ uint32_t smem_u32(const void* p) {
    uint32_t a;
    asm("{ .reg .u64 t; cvta.to.shared.u64 t, %1; cvt.u32.u64 %0, t; }" : "=r"(a) : "l"(p));
    return a;
}
__device__ __forceinline__ void ldm_x4(uint32_t* r, uint32_t addr) {
    asm volatile("ldmatrix.sync.aligned.m8n8.x4.shared.b16 {%0,%1,%2,%3}, [%4];"
                 : "=r"(r[0]), "=r"(r[1]), "=r"(r[2]), "=r"(r[3]) : "r"(addr));
}
__device__ __forceinline__ void ldm_x4_t(uint32_t* r, uint32_t addr) {
    asm volatile("ldmatrix.sync.aligned.m8n8.x4.trans.shared.b16 {%0,%1,%2,%3}, [%4];"
                 : "=r"(r[0]), "=r"(r[1]), "=r"(r[2]), "=r"(r[3]) : "r"(addr));
}
__device__ __forceinline__ void mma_bf16(float* c, const uint32_t* a, const uint32_t* b) {
    asm volatile(
        "mma.sync.aligned.m16n8k16.row.col.f32.bf16.bf16.f32 "
        "{%0,%1,%2,%3}, {%4,%5,%6,%7}, {%8,%9}, {%0,%1,%2,%3};"
        : "+f"(c[0]), "+f"(c[1]), "+f"(c[2]), "+f"(c[3])
        : "r"(a[0]), "r"(a[1]), "r"(a[2]), "r"(a[3]), "r"(b[0]), "r"(b[1]));
}
#define CP_ASYNC16(dst, src) \
    asm volatile("cp.async.cg.shared.global [%0], [%1], 16;" :: "r"(dst), "l"(src))
#define CP_COMMIT() asm volatile("cp.async.commit_group;" ::: "memory")
#define CP_WAIT0() asm volatile("cp.async.wait_group 0;" ::: "memory")

// ---------------- f32x2 helpers ----------------
__device__ __forceinline__ unsigned long long pk(float lo, float hi) {
    unsigned long long r;
    asm("mov.b64 %0, {%1,%2};" : "=l"(r) : "f"(lo), "f"(hi));
    return r;
}
__device__ __forceinline__ unsigned long long f2fma(unsigned long long a,
                                                    unsigned long long b,
                                                    unsigned long long c) {
    unsigned long long d;
    asm("fma.rn.f32x2 %0, %1, %2, %3;" : "=l"(d) : "l"(a), "l"(b), "l"(c));
    return d;
}
__device__ __forceinline__ float lof(unsigned long long v) { return __uint_as_float((unsigned)v); }
__device__ __forceinline__ float hif(unsigned long long v) { return __uint_as_float((unsigned)(v >> 32)); }

// ---------------- kernel 1: wh = h @ W + b, plus bf16 hi/lo split ------------
__global__ __launch_bounds__(256) void k_gemm_wh(const float* __restrict__ h,
                                                 const float* __restrict__ Wm,
                                                 const float* __restrict__ bias) {
    __shared__ float As[64][33];
    __shared__ float Bs[32][64];
    const int t = threadIdx.x;
    const int m0 = blockIdx.x * 64, n0 = blockIdx.y * 64;
    const int tx = t & 15, ty = t >> 4;
    unsigned long long acc2[4][2];
#pragma unroll
    for (int i = 0; i < 4; i++) { acc2[i][0] = 0ull; acc2[i][1] = 0ull; }
    for (int k0 = 0; k0 < FIN; k0 += 32) {
#pragma unroll
        for (int u = 0; u < 2; u++) {
            int idx = t + u * 256, r = idx >> 3, c = (idx & 7) * 4;
            float4 v = *(const float4*)(h + (size_t)(m0 + r) * FIN + k0 + c);
            As[r][c] = v.x; As[r][c + 1] = v.y; As[r][c + 2] = v.z; As[r][c + 3] = v.w;
        }
#pragma unroll
        for (int u = 0; u < 2; u++) {
            int idx = t + u * 256, r = idx >> 4, c = (idx & 15) * 4;
            *(float4*)(&Bs[r][c]) = *(const float4*)(Wm + (size_t)(k0 + r) * FOUT + n0 + c);
        }
        __syncthreads();
#pragma unroll
        for (int k = 0; k < 32; k++) {
            double2 bd = *(const double2*)(&Bs[k][tx * 4]);
            unsigned long long b01 = __double_as_longlong(bd.x);
            unsigned long long b23 = __double_as_longlong(bd.y);
#pragma unroll
            for (int i = 0; i < 4; i++) {
                float a = As[ty * 4 + i][k];
                unsigned long long ap = pk(a, a);
                acc2[i][0] = f2fma(ap, b01, acc2[i][0]);
                acc2[i][1] = f2fma(ap, b23, acc2[i][1]);
            }
        }
        __syncthreads();
    }
    const int n = n0 + tx * 4;
    float4 bv = *(const float4*)(bias + n);
#pragma unroll
    for (int i = 0; i < 4; i++) {
        float4 o;
        o.x = lof(acc2[i][0]) + bv.x; o.y = hif(acc2[i][0]) + bv.y;
        o.z = lof(acc2[i][1]) + bv.z; o.w = hif(acc2[i][1]) + bv.w;
        size_t gi = (size_t)(m0 + ty * 4 + i) * FOUT + n;
        *(float4*)(g_wh + gi) = o;
        __nv_bfloat162 ha = __floats2bfloat162_rn(o.x, o.y);
        __nv_bfloat162 hb = __floats2bfloat162_rn(o.z, o.w);
        __nv_bfloat162 la = __floats2bfloat162_rn(o.x - __bfloat162float(ha.x),
                                                  o.y - __bfloat162float(ha.y));
        __nv_bfloat162 lb = __floats2bfloat162_rn(o.z - __bfloat162float(hb.x),
                                                  o.w - __bfloat162float(hb.y));
        *(uint2*)(g_wh_hi + gi) = make_uint2(*(unsigned*)&ha, *(unsigned*)&hb);
        *(uint2*)(g_wh_lo + gi) = make_uint2(*(unsigned*)&la, *(unsigned*)&lb);
    }
}

// ---------------- kernel 2: f_src / f_dst ----------------
__global__ __launch_bounds__(256) void k_fsd(const float* __restrict__ a1,
                                             const float* __restrict__ a2,
                                             const float* __restrict__ ab) {
    const int warp = threadIdx.x >> 5, lane = threadIdx.x & 31;
    const int i = blockIdx.x * 8 + warp;
    const float4* row = (const float4*)(g_wh + (size_t)i * FOUT);
    const float4* A1 = (const float4*)a1;
    const float4* A2 = (const float4*)a2;
    float s1 = 0.f, s2 = 0.f;
#pragma unroll
    for (int u = 0; u < 2; u++) {
        float4 v = row[lane + u * 32], x = A1[lane + u * 32], y = A2[lane + u * 32];
        s1 += v.x * x.x + v.y * x.y + v.z * x.z + v.w * x.w;
        s2 += v.x * y.x + v.y * y.y + v.z * y.z + v.w * y.w;
    }
#pragma unroll
    for (int o = 16; o; o >>= 1) {
        s1 += __shfl_down_sync(0xffffffffu, s1, o);
        s2 += __shfl_down_sync(0xffffffffu, s2, o);
    }
    if (lane == 0) { g_fsrc[i] = s1 + ab[0]; g_fdst[i] = s2; }
}

// ---------------- kernel 3: softmax stats + bit-pack (256 thr, int4) --------
__global__ __launch_bounds__(256) void k_prep(const int* __restrict__ adj) {
    const int i = blockIdx.x, t = threadIdx.x;
    const float fs = g_fsrc[i];
    const int4* arow = (const int4*)(adj + (size_t)i * N);

    float fdv[16];
    const float4* fdp = (const float4*)g_fdst;
#pragma unroll
    for (int v = 0; v < 4; v++) {
        float4 f = fdp[t * 4 + v];
        fdv[v * 4 + 0] = f.x; fdv[v * 4 + 1] = f.y;
        fdv[v * 4 + 2] = f.z; fdv[v * 4 + 3] = f.w;
    }
    unsigned bits = 0;
#pragma unroll
    for (int q = 0; q < 4; q++) {
        int4 a = arow[t * 4 + q];
        if (a.x > 0) bits |= 1u << (q * 4 + 0);
        if (a.y > 0) bits |= 1u << (q * 4 + 1);
        if (a.z > 0) bits |= 1u << (q * 4 + 2);
        if (a.w > 0) bits |= 1u << (q * 4 + 3);
    }
    unsigned other = __shfl_xor_sync(0xffffffffu, bits, 1);
    if ((t & 1) == 0) g_mask[(size_t)i * 128 + (t >> 1)] = bits | (other << 16);

    float mx = -3.4e38f;
#pragma unroll
    for (int v = 0; v < 16; v++)
        if ((bits >> v) & 1u) mx = fmaxf(mx, fdv[v]);
#pragma unroll
    for (int o = 16; o; o >>= 1) mx = fmaxf(mx, __shfl_xor_sync(0xffffffffu, mx, o));
    __shared__ float redm[8];
    __shared__ float reds[8];
    if ((t & 31) == 0) redm[t >> 5] = mx;
    __syncthreads();
    float mxall = redm[0];
#pragma unroll
    for (int w = 1; w < 8; w++) mxall = fmaxf(mxall, redm[w]);
    float xm = fs + mxall;
    float mi = fmaxf(xm, ALPHA * xm);

    float s = 0.f;
#pragma unroll
    for (int v = 0; v < 16; v++)
        if ((bits >> v) & 1u) {
            float x = fs + fdv[v];
            s += __expf(fmaxf(x, ALPHA * x) - mi);
        }
#pragma unroll
    for (int o = 16; o; o >>= 1) s += __shfl_xor_sync(0xffffffffu, s, o);
    if ((t & 31) == 0) reds[t >> 5] = s;
    __syncthreads();
    if (t == 0) {
        float stot = 0.f;
#pragma unroll
        for (int w = 0; w < 8; w++) stot += reds[w];
        g_mi[i] = mi;
        g_rz[i] = (stot > 0.f) ? (1.f / stot) : 0.f;
    }
}

// ---------------- kernel 4: HMMA attention GEMM, 512 threads / 16 warps -----
// warp grid: mw = warp&1 (two 32-row halves), nw = warp>>1 (eight 32-col slices)
#define SM_FD 0
#define SM_MASK 8192
#define SM_STG0 24576
#define A_HI 0
#define A_LO 9216
#define B_HI 18432
#define B_LO 52224
#define STG 86016
#define SMEM_AT (SM_STG0 + 2 * STG)  // 196608

__global__ __launch_bounds__(512, 1) void k_attn_h() {
    extern __shared__ char smem[];
    const uint32_t sbase = smem_u32(smem);
    float* fd_s = (float*)(smem + SM_FD);
    unsigned* mask_s = (unsigned*)(smem + SM_MASK);
    const int t = threadIdx.x;
    const int lane = t & 31, warp = t >> 5;
    const int mw = warp & 1, nw = warp >> 1;
    const int i0 = blockIdx.x * 64;
    const int js = blockIdx.y;
    const int jorg = js * KCTA;

    // per-thread A-gen constants: thread generates weights for row i = t>>3
    const int gi = i0 + (t >> 3);
    const float fsi = g_fsrc[gi];
    const float mii = g_mi[gi];
    const float rzi = g_rz[gi];

    // preload fd (2048 floats) + mask (64 rows x 64 words)
    *(float4*)(fd_s + t * 4) = *(const float4*)(g_fdst + jorg + t * 4);
#pragma unroll
    for (int u = 0; u < 8; u++) {
        int idx = t + 512 * u;
        mask_s[idx] = g_mask[(size_t)(i0 + (idx >> 6)) * 128 + js * 64 + (idx & 63)];
    }
    __syncthreads();

    auto fill_B = [&](int c2, uint32_t stg_s) {
        size_t jg = (size_t)jorg + (size_t)c2 * 64;
#pragma unroll
        for (int u = 0; u < 4; u++) {
            int idx = t + 512 * u;
            int j = idx >> 5, dq = idx & 31;
            uint32_t dst = stg_s + B_HI + j * 528 + dq * 16;
            size_t src = (jg + j) * FOUT + dq * 8;
            CP_ASYNC16(dst, (const void*)(g_wh_hi + src));
            CP_ASYNC16(dst + (B_LO - B_HI), (const void*)(g_wh_lo + src));
        }
    };
    // each thread: row t>>3, j-octet t&7 (8 j values)
    auto fill_A = [&](int c2, char* stgp) {
        const int row = t >> 3, oct = t & 7;
        unsigned w = mask_s[row * 64 + c2 * 2 + (oct >> 2)];
        const int shift = (oct & 3) * 8;
        const float* fdp = fd_s + c2 * 64 + oct * 8;
        uint32_t hv[4], lv[4];
#pragma unroll
        for (int v = 0; v < 8; v += 2) {
            float e0 = 0.f, e1 = 0.f;
            if ((w >> (shift + v)) & 1u) {
                float x = fsi + fdp[v];
                e0 = __expf(fmaxf(x, ALPHA * x) - mii) * rzi;
            }
            if ((w >> (shift + v + 1)) & 1u) {
                float x = fsi + fdp[v + 1];
                e1 = __expf(fmaxf(x, ALPHA * x) - mii) * rzi;
            }
            __nv_bfloat162 h2 = __floats2bfloat162_rn(e0, e1);
            __nv_bfloat162 l2 = __floats2bfloat162_rn(e0 - __bfloat162float(h2.x),
                                                      e1 - __bfloat162float(h2.y));
            hv[v >> 1] = *(uint32_t*)&h2;
            lv[v >> 1] = *(uint32_t*)&l2;
        }
        char* pA = stgp + row * 144 + oct * 16;
        *(uint4*)(pA + A_HI) = make_uint4(hv[0], hv[1], hv[2], hv[3]);
        *(uint4*)(pA + A_LO) = make_uint4(lv[0], lv[1], lv[2], lv[3]);
    };

    float acc[2][4][4];
#pragma unroll
    for (int a = 0; a < 2; a++)
#pragma unroll
        for (int b = 0; b < 4; b++)
#pragma unroll
            for (int c = 0; c < 4; c++) acc[a][b][c] = 0.f;

    // ldmatrix per-thread base offsets
    const uint32_t a_off = (mw * 32 + (lane & 15)) * 144 + (lane >> 4) * 16;
    const uint32_t b_off = (lane & 15) * 528 + (nw * 32 + (lane >> 4) * 8) * 2;

    // prolog: fill chunk 0 into stage 0
    fill_B(0, sbase + SM_STG0);
    CP_COMMIT();
    fill_A(0, smem + SM_STG0);
    CP_WAIT0();
    __syncthreads();

#pragma unroll 1
    for (int c = 0; c < NCHUNK; c++) {
        const int s = c & 1;
        const uint32_t stg = SM_STG0 + (uint32_t)s * STG;
        const uint32_t stg2 = SM_STG0 + (uint32_t)(s ^ 1) * STG;
        const uint32_t Ah = sbase + stg + A_HI;
        const uint32_t Al = sbase + stg + A_LO;
        const uint32_t Bh = sbase + stg + B_HI;
        const uint32_t Bl = sbase + stg + B_LO;

        if (c + 1 < NCHUNK) { fill_B(c + 1, sbase + stg2); CP_COMMIT(); }

#pragma unroll
        for (int kk = 0; kk < 4; kk++) {
            uint32_t ah[2][4], al[2][4], bh[2][4], bl[2][4];
            const uint32_t ao = a_off + kk * 32;
            const uint32_t bo = b_off + kk * 8448;
#pragma unroll
            for (int mt = 0; mt < 2; mt++) {
                ldm_x4(ah[mt], Ah + mt * 2304 + ao);
                ldm_x4(al[mt], Al + mt * 2304 + ao);
            }
#pragma unroll
            for (int seg = 0; seg < 2; seg++) {
                ldm_x4_t(bh[seg], Bh + bo + seg * 32);
                ldm_x4_t(bl[seg], Bl + bo + seg * 32);
            }
#pragma unroll
            for (int mt = 0; mt < 2; mt++)
#pragma unroll
                for (int nb = 0; nb < 4; nb++) {
                    const uint32_t* bfh = &bh[nb >> 1][(nb & 1) * 2];
                    const uint32_t* bfl = &bl[nb >> 1][(nb & 1) * 2];
                    mma_bf16(acc[mt][nb], ah[mt], bfh);  // hi*hi
                    mma_bf16(acc[mt][nb], ah[mt], bfl);  // hi*lo
                    mma_bf16(acc[mt][nb], al[mt], bfh);  // lo*hi
                }
            if (kk == 0 && c + 1 < NCHUNK) fill_A(c + 1, smem + stg2);
        }

        CP_WAIT0();
        __syncthreads();
    }

    // epilogue: write partials
    float* base = g_part + (size_t)js * ((size_t)N * FOUT);
#pragma unroll
    for (int mt = 0; mt < 2; mt++) {
        int ir = i0 + mw * 32 + mt * 16 + (lane >> 2);
#pragma unroll
        for (int nb = 0; nb < 4; nb++) {
            int d = nw * 32 + nb * 8 + (lane & 3) * 2;
            *(float2*)(base + (size_t)ir * FOUT + d) =
                make_float2(acc[mt][nb][0], acc[mt][nb][1]);
            *(float2*)(base + (size_t)(ir + 8) * FOUT + d) =
                make_float2(acc[mt][nb][2], acc[mt][nb][3]);
        }
    }
}

// ---------------- kernel 5: combine partials + elu ----------------
__global__ __launch_bounds__(256) void k_comb(float* __restrict__ out) {
    const size_t idx = ((size_t)blockIdx.x * 256 + threadIdx.x) * 4;
    const size_t stride = (size_t)N * FOUT;
    float4 a = *(const float4*)(g_part + idx);
    float4 b = *(const float4*)(g_part + stride + idx);
    float4 o;
    o.x = a.x + b.x; o.y = a.y + b.y; o.z = a.z + b.z; o.w = a.w + b.w;
    o.x = o.x > 0.f ? o.x : (__expf(o.x) - 1.f);
    o.y = o.y > 0.f ? o.y : (__expf(o.y) - 1.f);
    o.z = o.z > 0.f ? o.z : (__expf(o.z) - 1.f);
    o.w = o.w > 0.f ? o.w : (__expf(o.w) - 1.f);
    *(float4*)(out + idx) = o;
}

// ---------------- launch ----------------
extern "C" void kernel_launch(void* const* d_in, const int* in_sizes, int n_in,
                              void* d_out, int out_size) {
    const int* adj = (const int*)d_in[0];
    const float* h = (const float*)d_in[1];
    const float* Wm = (const float*)d_in[2];
    const float* b = (const float*)d_in[3];
    const float* a1 = (const float*)d_in[4];
    const float* a2 = (const float*)d_in[5];
    const float* ab = (const float*)d_in[6];
    float* out = (float*)d_out;

    static bool attr_set = false;
    if (!attr_set) {
        cudaFuncSetAttribute(k_attn_h, cudaFuncAttributeMaxDynamicSharedMemorySize, SMEM_AT);
        attr_set = true;
    }

    k_gemm_wh<<<dim3(N / 64, FOUT / 64), 256>>>(h, Wm, b);
    k_fsd<<<N / 8, 256>>>(a1, a2, ab);
    k_prep<<<N, 256>>>(adj);
    k_attn_h<<<dim3(N / 64, JSPLIT), 512, SMEM_AT>>>();
    k_comb<<<(N * FOUT) / 1024, 256>>>(out);
}